// round 4
// baseline (speedup 1.0000x reference)
#include <cuda_runtime.h>
#include <math.h>

// Problem constants
#define B_     16
#define HH     28
#define WW     28
#define HW     784
#define C_ALL  3072
#define C4     2048
#define C3     1024
#define H4     14
#define HW4    196
#define NL     9
#define NK     2000

// Partition of the channel dim for the ab (landmark logit) pass
#define NCH    24
#define CCH    128   // channels per chunk; 16 chunks cover l4, 8 cover l3

// Output layout: class_scores (16*2000), maps (16*9*784), all_features (16*3072*9)
#define CLS_OFF  0
#define MAPS_OFF (B_*NK)                  // 32000
#define FEAT_OFF (MAPS_OFF + B_*NL*HW)    // 144896

// Scratch (static __device__ arrays: allocation-free)
__device__ float g_asq[NL];
__device__ float g_part[(size_t)B_*HW*NCH*NL];   // ~10.8 MB partial ab sums
__device__ float g_modavg[(size_t)C_ALL*B_];     // [c][b] transposed for float4 reads

// ---------------------------------------------------------------------------
// K0: a_sq[l] = ||W_land[l]||^2
// ---------------------------------------------------------------------------
__global__ void k_asq(const float* __restrict__ Wl) {
    int warp = threadIdx.x >> 5, lane = threadIdx.x & 31;
    if (warp < NL) {
        float s = 0.f;
        for (int i = lane; i < C_ALL; i += 32) {
            float w = Wl[warp * C_ALL + i];
            s = fmaf(w, w, s);
        }
        #pragma unroll
        for (int o = 16; o; o >>= 1) s += __shfl_xor_sync(0xffffffffu, s, o);
        if (lane == 0) g_asq[warp] = s;
    }
}

// ---------------------------------------------------------------------------
// K1: partial ab[b,l,px] over a channel chunk. Block = (chunk, b), 196 threads,
// each thread owns 4 consecutive pixels (196*4 = 784 = full image).
// l4 channels are upsampled on the fly from SMEM-staged 14x14 rows.
// ---------------------------------------------------------------------------
__global__ __launch_bounds__(196) void k_ab(const float* __restrict__ l3,
                                            const float* __restrict__ l4,
                                            const float* __restrict__ Wl) {
    __shared__ float sW[NL * CCH];      // 4.5 KB
    __shared__ float sRow[8 * HW4];     // 6.1 KB: 8 staged l4 channel rows

    int b = blockIdx.y, chunk = blockIdx.x;
    int c0 = chunk * CCH;
    int tid = threadIdx.x;

    for (int i = tid; i < NL * CCH; i += 196) {
        int l = i / CCH, cc = i - l * CCH;
        sW[i] = Wl[l * C_ALL + c0 + cc];
    }

    int px = tid * 4;
    int py = px / WW, pxx = px - py * WW;

    float acc[NL][4];
    #pragma unroll
    for (int l = 0; l < NL; l++)
        #pragma unroll
        for (int j = 0; j < 4; j++) acc[l][j] = 0.f;

    if (chunk < 16) {
        // ---- l4 region: bilinear upsample (half-pixel centers, edge-renorm) ----
        float cyf = 0.5f * (float)py - 0.25f;
        int iyf = (int)floorf(cyf);
        float wy = cyf - (float)iyf;
        int iy0 = iyf < 0 ? 0 : iyf;
        int iy1 = (iyf + 1) > 13 ? 13 : (iyf + 1);

        int oa0[4], oa1[4], ob0[4], ob1[4];
        float wx[4];
        #pragma unroll
        for (int j = 0; j < 4; j++) {
            float cxf = 0.5f * (float)(pxx + j) - 0.25f;
            int ixf = (int)floorf(cxf);
            wx[j] = cxf - (float)ixf;
            int x0 = ixf < 0 ? 0 : ixf;
            int x1 = (ixf + 1) > 13 ? 13 : (ixf + 1);
            oa0[j] = iy0 * H4 + x0; oa1[j] = iy0 * H4 + x1;
            ob0[j] = iy1 * H4 + x0; ob1[j] = iy1 * H4 + x1;
        }

        const float* l4b = l4 + ((size_t)b * C4 + c0) * HW4;
        __syncthreads();                       // sW visible
        for (int cg = 0; cg < CCH; cg += 8) {
            const float4* src = (const float4*)(l4b + (size_t)cg * HW4);
            ((float4*)sRow)[tid]       = src[tid];
            ((float4*)sRow)[tid + 196] = src[tid + 196];
            __syncthreads();
            #pragma unroll
            for (int cc = 0; cc < 8; cc++) {
                const float* r = sRow + cc * HW4;
                float xv[4];
                #pragma unroll
                for (int j = 0; j < 4; j++) {
                    float a0 = r[oa0[j]], a1 = r[oa1[j]];
                    float b0 = r[ob0[j]], b1 = r[ob1[j]];
                    float t = fmaf(wx[j], a1 - a0, a0);
                    float u = fmaf(wx[j], b1 - b0, b0);
                    xv[j] = fmaf(wy, u - t, t);
                }
                int c = cg + cc;
                #pragma unroll
                for (int l = 0; l < NL; l++) {
                    float w = sW[l * CCH + c];
                    #pragma unroll
                    for (int j = 0; j < 4; j++)
                        acc[l][j] = fmaf(w, xv[j], acc[l][j]);
                }
            }
            __syncthreads();
        }
    } else {
        // ---- l3 region: direct coalesced float4 loads ----
        __syncthreads();                       // sW visible
        const float* x3 = l3 + ((size_t)b * C3 + (c0 - C4)) * HW + px;
        for (int c = 0; c < CCH; c++) {
            float4 xv = *(const float4*)(x3 + (size_t)c * HW);
            #pragma unroll
            for (int l = 0; l < NL; l++) {
                float w = sW[l * CCH + c];
                acc[l][0] = fmaf(w, xv.x, acc[l][0]);
                acc[l][1] = fmaf(w, xv.y, acc[l][1]);
                acc[l][2] = fmaf(w, xv.z, acc[l][2]);
                acc[l][3] = fmaf(w, xv.w, acc[l][3]);
            }
        }
    }

    #pragma unroll
    for (int j = 0; j < 4; j++) {
        float* dst = g_part + (((size_t)(b * HW + px + j)) * NCH + chunk) * NL;
        #pragma unroll
        for (int l = 0; l < NL; l++) dst[l] = acc[l][j];
    }
}

// ---------------------------------------------------------------------------
// K2: sum partials, logits = 2*ab - a_sq (b_sq cancels in softmax), softmax,
// write maps to d_out.
// ---------------------------------------------------------------------------
__global__ void k_softmax(float* __restrict__ out) {
    int idx = blockIdx.x * blockDim.x + threadIdx.x;
    if (idx >= B_ * HW) return;
    int b = idx / HW, px = idx - b * HW;

    float s[NL];
    #pragma unroll
    for (int l = 0; l < NL; l++) s[l] = 0.f;

    const float4* p4 = (const float4*)(g_part + (size_t)idx * NCH * NL);
    #pragma unroll
    for (int i = 0; i < (NCH * NL) / 4; i++) {
        float4 v = p4[i];
        s[(4 * i + 0) % NL] += v.x;
        s[(4 * i + 1) % NL] += v.y;
        s[(4 * i + 2) % NL] += v.z;
        s[(4 * i + 3) % NL] += v.w;
    }

    float lg[NL], m = -1e30f;
    #pragma unroll
    for (int l = 0; l < NL; l++) {
        lg[l] = 2.f * s[l] - g_asq[l];
        m = fmaxf(m, lg[l]);
    }
    float e[NL], den = 0.f;
    #pragma unroll
    for (int l = 0; l < NL; l++) { e[l] = __expf(lg[l] - m); den += e[l]; }
    float inv = 1.f / den;

    float* mp = out + MAPS_OFF + (size_t)b * NL * HW + px;
    #pragma unroll
    for (int l = 0; l < NL; l++) mp[(size_t)l * HW] = e[l] * inv;
}

// ---------------------------------------------------------------------------
// K3: all_features[b,c,l] = (1/784) * sum_px maps[b,l,px] * x[b,c,px].
// Block = (cblk of 32 channels, b); 8 warps, each warp owns 4 channels;
// maps staged once in SMEM, l4 rows staged per-warp, maps loads amortized
// over the 4 channels.
// ---------------------------------------------------------------------------
__global__ __launch_bounds__(256) void k_feat(const float* __restrict__ l3,
                                              const float* __restrict__ l4,
                                              float* __restrict__ out) {
    extern __shared__ float sm[];
    float* sMaps = sm;                 // NL*HW = 7056 floats
    float* sL4   = sm + NL * HW;       // 8 warps * 4 ch * 196 = 6272 floats

    int b = blockIdx.y, cblk = blockIdx.x;
    int tid = threadIdx.x, warp = tid >> 5, lane = tid & 31;

    const float* mp = out + MAPS_OFF + (size_t)b * NL * HW;
    for (int i = tid; i < NL * HW; i += 256) sMaps[i] = mp[i];
    __syncthreads();

    int cbase = cblk * 32 + warp * 4;
    float acc[4][NL];
    #pragma unroll
    for (int ch = 0; ch < 4; ch++)
        #pragma unroll
        for (int l = 0; l < NL; l++) acc[ch][l] = 0.f;

    if (cbase < C4) {
        float* st = sL4 + warp * (4 * HW4);
        #pragma unroll
        for (int ch = 0; ch < 4; ch++) {
            const float* row = l4 + ((size_t)b * C4 + cbase + ch) * HW4;
            for (int i = lane; i < HW4; i += 32) st[ch * HW4 + i] = row[i];
        }
        __syncwarp();
        for (int px = lane; px < HW; px += 32) {
            int py = px / WW, pxx = px - py * WW;
            float cyf = 0.5f * (float)py - 0.25f;
            int iyf = (int)floorf(cyf);
            float wy = cyf - (float)iyf;
            int iy0 = iyf < 0 ? 0 : iyf;
            int iy1 = (iyf + 1) > 13 ? 13 : (iyf + 1);
            float cxf = 0.5f * (float)pxx - 0.25f;
            int ixf = (int)floorf(cxf);
            float wx = cxf - (float)ixf;
            int ix0 = ixf < 0 ? 0 : ixf;
            int ix1 = (ixf + 1) > 13 ? 13 : (ixf + 1);
            int oa0 = iy0 * H4 + ix0, oa1 = iy0 * H4 + ix1;
            int ob0 = iy1 * H4 + ix0, ob1 = iy1 * H4 + ix1;

            float m9[NL];
            #pragma unroll
            for (int l = 0; l < NL; l++) m9[l] = sMaps[l * HW + px];

            #pragma unroll
            for (int ch = 0; ch < 4; ch++) {
                const float* r = st + ch * HW4;
                float a0 = r[oa0], a1 = r[oa1], b0 = r[ob0], b1 = r[ob1];
                float t = fmaf(wx, a1 - a0, a0);
                float u = fmaf(wx, b1 - b0, b0);
                float xv = fmaf(wy, u - t, t);
                #pragma unroll
                for (int l = 0; l < NL; l++)
                    acc[ch][l] = fmaf(xv, m9[l], acc[ch][l]);
            }
        }
    } else {
        const float* x3 = l3 + ((size_t)b * C3 + (cbase - C4)) * HW;
        for (int px = lane; px < HW; px += 32) {
            float m9[NL];
            #pragma unroll
            for (int l = 0; l < NL; l++) m9[l] = sMaps[l * HW + px];
            #pragma unroll
            for (int ch = 0; ch < 4; ch++) {
                float xv = x3[(size_t)ch * HW + px];
                #pragma unroll
                for (int l = 0; l < NL; l++)
                    acc[ch][l] = fmaf(xv, m9[l], acc[ch][l]);
            }
        }
    }

    #pragma unroll
    for (int ch = 0; ch < 4; ch++)
        #pragma unroll
        for (int l = 0; l < NL; l++) {
            float v = acc[ch][l];
            #pragma unroll
            for (int o = 16; o; o >>= 1) v += __shfl_xor_sync(0xffffffffu, v, o);
            acc[ch][l] = v;
        }

    if (lane == 0) {
        const float sc = 1.0f / (float)HW;
        #pragma unroll
        for (int ch = 0; ch < 4; ch++)
            #pragma unroll
            for (int l = 0; l < NL; l++)
                out[FEAT_OFF + ((size_t)b * C_ALL + cbase + ch) * NL + l] =
                    acc[ch][l] * sc;
    }
}

// ---------------------------------------------------------------------------
// K4: mod_avg[c][b] = (1/8) * sum_{l<8} feat[b,c,l] * modulation[c,l]
// (stored transposed so K5 can read 16 batches as 4x float4)
// ---------------------------------------------------------------------------
__global__ void k_modavg(const float* __restrict__ mod, const float* __restrict__ out) {
    int idx = blockIdx.x * 256 + threadIdx.x;
    if (idx >= C_ALL * B_) return;
    int c = idx >> 4, b = idx & 15;
    const float* f = out + FEAT_OFF + ((size_t)b * C_ALL + c) * NL;
    const float* md = mod + c * NL;
    float s = 0.f;
    #pragma unroll
    for (int l = 0; l < 8; l++) s = fmaf(f[l], md[l], s);
    g_modavg[(size_t)c * B_ + b] = s * 0.125f;
}

// ---------------------------------------------------------------------------
// K5: class_scores[b,k] = sum_c W_class[k,c] * mod_avg[c][b]
// Block per k; coalesced W_class row read; 16 batch accumulators.
// ---------------------------------------------------------------------------
__global__ __launch_bounds__(256) void k_cls(const float* __restrict__ Wc,
                                             float* __restrict__ out) {
    int k = blockIdx.x, tid = threadIdx.x, warp = tid >> 5, lane = tid & 31;
    const float* wr = Wc + (size_t)k * C_ALL;

    float acc[B_];
    #pragma unroll
    for (int b = 0; b < B_; b++) acc[b] = 0.f;

    for (int c = tid; c < C_ALL; c += 256) {
        float w = wr[c];
        const float4* mv = (const float4*)(g_modavg + (size_t)c * B_);
        #pragma unroll
        for (int q = 0; q < 4; q++) {
            float4 m = mv[q];
            acc[4 * q + 0] = fmaf(w, m.x, acc[4 * q + 0]);
            acc[4 * q + 1] = fmaf(w, m.y, acc[4 * q + 1]);
            acc[4 * q + 2] = fmaf(w, m.z, acc[4 * q + 2]);
            acc[4 * q + 3] = fmaf(w, m.w, acc[4 * q + 3]);
        }
    }

    __shared__ float red[8][B_];
    #pragma unroll
    for (int b = 0; b < B_; b++) {
        float v = acc[b];
        #pragma unroll
        for (int o = 16; o; o >>= 1) v += __shfl_xor_sync(0xffffffffu, v, o);
        acc[b] = v;
    }
    if (lane == 0)
        #pragma unroll
        for (int b = 0; b < B_; b++) red[warp][b] = acc[b];
    __syncthreads();
    if (tid < B_) {
        float s = 0.f;
        #pragma unroll
        for (int w = 0; w < 8; w++) s += red[w][tid];
        out[(size_t)tid * NK + k] = s;
    }
}

// ---------------------------------------------------------------------------
extern "C" void kernel_launch(void* const* d_in, const int* in_sizes, int n_in,
                              void* d_out, int out_size) {
    const float* l3  = (const float*)d_in[0];
    const float* l4  = (const float*)d_in[1];
    const float* Wl  = (const float*)d_in[2];
    const float* Wc  = (const float*)d_in[3];
    const float* mod = (const float*)d_in[4];
    float* out = (float*)d_out;

    k_asq<<<1, 288>>>(Wl);
    k_ab<<<dim3(NCH, B_), 196>>>(l3, l4, Wl);
    k_softmax<<<(B_ * HW + 255) / 256, 256>>>(out);

    size_t sm3 = (size_t)(NL * HW + 8 * 4 * HW4) * sizeof(float);  // 53312 B
    cudaFuncSetAttribute(k_feat, cudaFuncAttributeMaxDynamicSharedMemorySize, (int)sm3);
    k_feat<<<dim3(96, B_), 256, sm3>>>(l3, l4, out);

    k_modavg<<<(C_ALL * B_ + 255) / 256, 256>>>(mod, out);
    k_cls<<<NK, 256>>>(Wc, out);
}

// round 5
// speedup vs baseline: 1.1190x; 1.1190x over previous
#include <cuda_runtime.h>
#include <math.h>

// Problem constants
#define B_     16
#define HH     28
#define WW     28
#define HW     784
#define C_ALL  3072
#define C4     2048
#define C3     1024
#define H4     14
#define HW4    196
#define NL     9
#define NK     2000

#define NCH4   32   // l4 chunks (64 ch each) over 2048, contraction at 14x14
#define NCH3   16   // l3 chunks (64 ch each) over 1024, contraction at 28x28

// Output layout: class_scores (16*2000), maps (16*9*784), all_features (16*3072*9)
#define CLS_OFF  0
#define MAPS_OFF (B_*NK)                  // 32000
#define FEAT_OFF (MAPS_OFF + B_*NL*HW)    // 144896

// Scratch (static __device__ arrays: allocation-free)
__device__ float g_asq[NL];
__device__ float g_p4[(size_t)B_*NCH4*NL*HW4];        // 3.6 MB  partial ab4
__device__ float g_part3[(size_t)B_*HW*NCH3*NL];      // 7.2 MB  partial ab3
__device__ float g_ab4[(size_t)B_*NL*HW4];            // summed ab4 (14x14)
__device__ float g_md[(size_t)B_*NL*HW4];             // adjoint-downsampled maps
__device__ float g_modavg[(size_t)C_ALL*B_];          // [c][b]

// ---------------------------------------------------------------------------
// K0: a_sq[l] = ||W_land[l]||^2
// ---------------------------------------------------------------------------
__global__ void k_asq(const float* __restrict__ Wl) {
    int warp = threadIdx.x >> 5, lane = threadIdx.x & 31;
    if (warp < NL) {
        float s = 0.f;
        for (int i = lane; i < C_ALL; i += 32) {
            float w = Wl[warp * C_ALL + i];
            s = fmaf(w, w, s);
        }
        #pragma unroll
        for (int o = 16; o; o >>= 1) s += __shfl_xor_sync(0xffffffffu, s, o);
        if (lane == 0) g_asq[warp] = s;
    }
}

// ---------------------------------------------------------------------------
// K1: fused landmark-logit contraction.
//  chunk <  NCH4 : ab4 partials at 14x14 over 64 l4 channels (no upsample!)
//  chunk >= NCH4 : ab3 partials at 28x28 over 64 l3 channels
// ---------------------------------------------------------------------------
__global__ __launch_bounds__(196) void k_ab(const float* __restrict__ l3,
                                            const float* __restrict__ l4,
                                            const float* __restrict__ Wl) {
    __shared__ float sW[NL * 64];
    __shared__ float sRow[8 * HW4];

    int b = blockIdx.y, chunk = blockIdx.x, tid = threadIdx.x;

    if (chunk < NCH4) {
        int c0 = chunk * 64;
        for (int i = tid; i < NL * 64; i += 196) {
            int l = i >> 6, cc = i & 63;
            sW[i] = Wl[l * C_ALL + c0 + cc];
        }
        const float* l4b = l4 + ((size_t)b * C4 + c0) * HW4;

        float acc[NL];
        #pragma unroll
        for (int l = 0; l < NL; l++) acc[l] = 0.f;

        __syncthreads();
        for (int cg = 0; cg < 64; cg += 8) {
            const float4* src = (const float4*)(l4b + (size_t)cg * HW4);
            ((float4*)sRow)[tid]       = src[tid];
            ((float4*)sRow)[tid + 196] = src[tid + 196];
            __syncthreads();
            #pragma unroll
            for (int cc = 0; cc < 8; cc++) {
                float x = sRow[cc * HW4 + tid];
                #pragma unroll
                for (int l = 0; l < NL; l++)
                    acc[l] = fmaf(sW[l * 64 + cg + cc], x, acc[l]);
            }
            __syncthreads();
        }
        float* dst = g_p4 + ((size_t)(b * NCH4 + chunk) * NL) * HW4 + tid;
        #pragma unroll
        for (int l = 0; l < NL; l++) dst[(size_t)l * HW4] = acc[l];
    } else {
        int ch3 = chunk - NCH4;
        int c0 = ch3 * 64;
        for (int i = tid; i < NL * 64; i += 196) {
            int l = i >> 6, cc = i & 63;
            sW[i] = Wl[l * C_ALL + C4 + c0 + cc];
        }
        int px = tid * 4;
        float acc[NL][4];
        #pragma unroll
        for (int l = 0; l < NL; l++)
            #pragma unroll
            for (int j = 0; j < 4; j++) acc[l][j] = 0.f;

        const float* x3 = l3 + ((size_t)b * C3 + c0) * HW + px;
        __syncthreads();
        for (int c = 0; c < 64; c++) {
            float4 xv = *(const float4*)(x3 + (size_t)c * HW);
            #pragma unroll
            for (int l = 0; l < NL; l++) {
                float w = sW[l * 64 + c];
                acc[l][0] = fmaf(w, xv.x, acc[l][0]);
                acc[l][1] = fmaf(w, xv.y, acc[l][1]);
                acc[l][2] = fmaf(w, xv.z, acc[l][2]);
                acc[l][3] = fmaf(w, xv.w, acc[l][3]);
            }
        }
        #pragma unroll
        for (int j = 0; j < 4; j++) {
            float* dst = g_part3 + (((size_t)(b * HW + px + j)) * NCH3 + ch3) * NL;
            #pragma unroll
            for (int l = 0; l < NL; l++) dst[l] = acc[l][j];
        }
    }
}

// ---------------------------------------------------------------------------
// K2: reduce ab4 partials over chunks: g_ab4[b][l][q]
// ---------------------------------------------------------------------------
__global__ void k_red4() {
    int idx = blockIdx.x * 256 + threadIdx.x;
    if (idx >= B_ * NL * HW4) return;
    int b = idx / (NL * HW4), r = idx - b * (NL * HW4);
    float s = 0.f;
    const float* p = g_p4 + (size_t)b * NCH4 * NL * HW4 + r;
    #pragma unroll
    for (int ch = 0; ch < NCH4; ch++) s += p[(size_t)ch * NL * HW4];
    g_ab4[idx] = s;
}

// ---------------------------------------------------------------------------
// K3: upsample ab4 (9 channels only!), add ab3 partials, softmax, write maps.
// ---------------------------------------------------------------------------
__global__ void k_softmax(float* __restrict__ out) {
    int idx = blockIdx.x * blockDim.x + threadIdx.x;
    if (idx >= B_ * HW) return;
    int b = idx / HW, px = idx - b * HW;
    int py = px / WW, pxx = px - py * WW;

    // bilinear stencil (identical arithmetic to reference upsample)
    float cyf = 0.5f * (float)py - 0.25f;
    int iyf = (int)floorf(cyf);
    float wy = cyf - (float)iyf;
    int iy0 = iyf < 0 ? 0 : iyf;
    int iy1 = (iyf + 1) > 13 ? 13 : (iyf + 1);
    float cxf = 0.5f * (float)pxx - 0.25f;
    int ixf = (int)floorf(cxf);
    float wx = cxf - (float)ixf;
    int ix0 = ixf < 0 ? 0 : ixf;
    int ix1 = (ixf + 1) > 13 ? 13 : (ixf + 1);
    int oa0 = iy0 * H4 + ix0, oa1 = iy0 * H4 + ix1;
    int ob0 = iy1 * H4 + ix0, ob1 = iy1 * H4 + ix1;

    float s[NL];
    const float* A = g_ab4 + (size_t)b * NL * HW4;
    #pragma unroll
    for (int l = 0; l < NL; l++) {
        const float* r = A + l * HW4;
        float a0 = r[oa0], a1 = r[oa1], b0 = r[ob0], b1 = r[ob1];
        float t = fmaf(wx, a1 - a0, a0);
        float u = fmaf(wx, b1 - b0, b0);
        s[l] = fmaf(wy, u - t, t);
    }

    // ab3 partials: contiguous NCH3*NL = 144 floats
    const float4* p4 = (const float4*)(g_part3 + (size_t)idx * NCH3 * NL);
    #pragma unroll
    for (int i = 0; i < (NCH3 * NL) / 4; i++) {
        float4 v = p4[i];
        s[(4 * i + 0) % NL] += v.x;
        s[(4 * i + 1) % NL] += v.y;
        s[(4 * i + 2) % NL] += v.z;
        s[(4 * i + 3) % NL] += v.w;
    }

    float lg[NL], m = -1e30f;
    #pragma unroll
    for (int l = 0; l < NL; l++) {
        lg[l] = 2.f * s[l] - g_asq[l];
        m = fmaxf(m, lg[l]);
    }
    float e[NL], den = 0.f;
    #pragma unroll
    for (int l = 0; l < NL; l++) { e[l] = __expf(lg[l] - m); den += e[l]; }
    float inv = 1.f / den;

    float* mp = out + MAPS_OFF + (size_t)b * NL * HW + px;
    #pragma unroll
    for (int l = 0; l < NL; l++) mp[(size_t)l * HW] = e[l] * inv;
}

// ---------------------------------------------------------------------------
// K4: adjoint-downsample of maps: md[b][l][q] = sum_px maps[b][l][px]*w(px,q).
// Gather form: each 14x14 cell receives from <=4x4 output pixels.
// ---------------------------------------------------------------------------
__global__ void k_mapsdown(const float* __restrict__ out) {
    int idx = blockIdx.x * 256 + threadIdx.x;
    if (idx >= B_ * NL * HW4) return;
    int b = idx / (NL * HW4), r = idx - b * (NL * HW4);
    int l = r / HW4, q = r - l * HW4;
    int iy = q / H4, ix = q - iy * H4;

    const float* mp = out + MAPS_OFF + ((size_t)b * NL + l) * HW;

    float s = 0.f;
    #pragma unroll
    for (int dy = 0; dy < 4; dy++) {
        int py = 2 * iy - 1 + dy;
        if (py < 0 || py > 27) continue;
        float cy = 0.5f * (float)py - 0.25f;
        int iyf = (int)floorf(cy);
        float wy = cy - (float)iyf;
        int r0 = iyf < 0 ? 0 : iyf;
        int r1 = (iyf + 1) > 13 ? 13 : (iyf + 1);
        float wr = (r0 == iy ? 1.f - wy : 0.f) + (r1 == iy ? wy : 0.f);
        if (wr == 0.f) continue;
        #pragma unroll
        for (int dx = 0; dx < 4; dx++) {
            int pxx = 2 * ix - 1 + dx;
            if (pxx < 0 || pxx > 27) continue;
            float cx = 0.5f * (float)pxx - 0.25f;
            int ixf = (int)floorf(cx);
            float wxv = cx - (float)ixf;
            int c0 = ixf < 0 ? 0 : ixf;
            int c1 = (ixf + 1) > 13 ? 13 : (ixf + 1);
            float wc = (c0 == ix ? 1.f - wxv : 0.f) + (c1 == ix ? wxv : 0.f);
            if (wc == 0.f) continue;
            s = fmaf(wr * wc, mp[py * WW + pxx], s);
        }
    }
    g_md[idx] = s;
}

// ---------------------------------------------------------------------------
// K5: all_features. Thread owns one (c,l) output; no cross-thread reduction.
//  cg <  64 : l4 channels, K=196 against g_md   (adjoint trick)
//  cg >= 64 : l3 channels, K=784 against maps (4 px-chunks of 196)
// Block = 288 threads = 32 channels x 9 landmarks.
// ---------------------------------------------------------------------------
__global__ __launch_bounds__(288) void k_feat(const float* __restrict__ l3,
                                              const float* __restrict__ l4,
                                              float* __restrict__ out) {
    __shared__ float4 sX[32 * 49];   // 32 channels x 196 px
    __shared__ float4 sM[NL * 49];   // 9 maps x 196 px

    int b = blockIdx.y, cg = blockIdx.x, tid = threadIdx.x;
    int c_local = tid / 9, l = tid - c_local * 9;

    float4 a = make_float4(0.f, 0.f, 0.f, 0.f);

    if (cg < 64) {
        int c0 = cg * 32;
        // stage md (contiguous per batch)
        const float4* md4 = (const float4*)(g_md + (size_t)b * NL * HW4);
        for (int i = tid; i < NL * 49; i += 288) sM[i] = md4[i];
        // stage 32 contiguous l4 channel rows (fully contiguous block)
        const float4* src = (const float4*)(l4 + ((size_t)b * C4 + c0) * HW4);
        for (int i = tid; i < 32 * 49; i += 288) sX[i] = src[i];
        __syncthreads();

        const float4* xr = sX + c_local * 49;
        const float4* mr = sM + l * 49;
        #pragma unroll 7
        for (int i = 0; i < 49; i++) {
            float4 x = xr[i], m = mr[i];
            a.x = fmaf(x.x, m.x, a.x);
            a.y = fmaf(x.y, m.y, a.y);
            a.z = fmaf(x.z, m.z, a.z);
            a.w = fmaf(x.w, m.w, a.w);
        }
        float res = ((a.x + a.y) + (a.z + a.w)) * (1.0f / (float)HW);
        out[FEAT_OFF + ((size_t)b * C_ALL + c0 + c_local) * NL + l] = res;
    } else {
        int c0 = (cg - 64) * 32;   // within l3
        const float* mbase = out + MAPS_OFF + (size_t)b * NL * HW;
        const float* xbase = l3 + ((size_t)b * C3 + c0) * HW;

        for (int pc = 0; pc < 4; pc++) {
            for (int i = tid; i < NL * 49; i += 288) {
                int ll = i / 49, j = i - ll * 49;
                sM[i] = ((const float4*)(mbase + (size_t)ll * HW + pc * HW4))[j];
            }
            for (int i = tid; i < 32 * 49; i += 288) {
                int cc = i / 49, j = i - cc * 49;
                sX[i] = ((const float4*)(xbase + (size_t)cc * HW + pc * HW4))[j];
            }
            __syncthreads();
            const float4* xr = sX + c_local * 49;
            const float4* mr = sM + l * 49;
            #pragma unroll 7
            for (int i = 0; i < 49; i++) {
                float4 x = xr[i], m = mr[i];
                a.x = fmaf(x.x, m.x, a.x);
                a.y = fmaf(x.y, m.y, a.y);
                a.z = fmaf(x.z, m.z, a.z);
                a.w = fmaf(x.w, m.w, a.w);
            }
            __syncthreads();
        }
        float res = ((a.x + a.y) + (a.z + a.w)) * (1.0f / (float)HW);
        out[FEAT_OFF + ((size_t)b * C_ALL + C4 + c0 + c_local) * NL + l] = res;
    }
}

// ---------------------------------------------------------------------------
// K6: mod_avg[c][b] = (1/8) * sum_{l<8} feat[b,c,l] * modulation[c,l]
// ---------------------------------------------------------------------------
__global__ void k_modavg(const float* __restrict__ mod, const float* __restrict__ out) {
    int idx = blockIdx.x * 256 + threadIdx.x;
    if (idx >= C_ALL * B_) return;
    int c = idx >> 4, b = idx & 15;
    const float* f = out + FEAT_OFF + ((size_t)b * C_ALL + c) * NL;
    const float* md = mod + c * NL;
    float s = 0.f;
    #pragma unroll
    for (int l = 0; l < 8; l++) s = fmaf(f[l], md[l], s);
    g_modavg[(size_t)c * B_ + b] = s * 0.125f;
}

// ---------------------------------------------------------------------------
// K7: class_scores[b,k] = sum_c W_class[k,c] * mod_avg[c][b]
// ---------------------------------------------------------------------------
__global__ __launch_bounds__(256) void k_cls(const float* __restrict__ Wc,
                                             float* __restrict__ out) {
    int k = blockIdx.x, tid = threadIdx.x, warp = tid >> 5, lane = tid & 31;
    const float* wr = Wc + (size_t)k * C_ALL;

    float acc[B_];
    #pragma unroll
    for (int b = 0; b < B_; b++) acc[b] = 0.f;

    for (int c = tid; c < C_ALL; c += 256) {
        float w = wr[c];
        const float4* mv = (const float4*)(g_modavg + (size_t)c * B_);
        #pragma unroll
        for (int q = 0; q < 4; q++) {
            float4 m = mv[q];
            acc[4 * q + 0] = fmaf(w, m.x, acc[4 * q + 0]);
            acc[4 * q + 1] = fmaf(w, m.y, acc[4 * q + 1]);
            acc[4 * q + 2] = fmaf(w, m.z, acc[4 * q + 2]);
            acc[4 * q + 3] = fmaf(w, m.w, acc[4 * q + 3]);
        }
    }

    __shared__ float red[8][B_];
    #pragma unroll
    for (int b = 0; b < B_; b++) {
        float v = acc[b];
        #pragma unroll
        for (int o = 16; o; o >>= 1) v += __shfl_xor_sync(0xffffffffu, v, o);
        acc[b] = v;
    }
    if (lane == 0)
        #pragma unroll
        for (int b = 0; b < B_; b++) red[warp][b] = acc[b];
    __syncthreads();
    if (tid < B_) {
        float s = 0.f;
        #pragma unroll
        for (int w = 0; w < 8; w++) s += red[w][tid];
        out[(size_t)tid * NK + k] = s;
    }
}

// ---------------------------------------------------------------------------
extern "C" void kernel_launch(void* const* d_in, const int* in_sizes, int n_in,
                              void* d_out, int out_size) {
    const float* l3  = (const float*)d_in[0];
    const float* l4  = (const float*)d_in[1];
    const float* Wl  = (const float*)d_in[2];
    const float* Wc  = (const float*)d_in[3];
    const float* mod = (const float*)d_in[4];
    float* out = (float*)d_out;

    k_asq<<<1, 288>>>(Wl);
    k_ab<<<dim3(NCH4 + NCH3, B_), 196>>>(l3, l4, Wl);
    k_red4<<<(B_ * NL * HW4 + 255) / 256, 256>>>();
    k_softmax<<<(B_ * HW + 255) / 256, 256>>>(out);
    k_mapsdown<<<(B_ * NL * HW4 + 255) / 256, 256>>>(out);
    k_feat<<<dim3(96, B_), 288>>>(l3, l4, out);
    k_modavg<<<(C_ALL * B_ + 255) / 256, 256>>>(mod, out);
    k_cls<<<NK, 256>>>(Wc, out);
}

// round 6
// speedup vs baseline: 1.3026x; 1.1640x over previous
#include <cuda_runtime.h>
#include <math.h>

// Problem constants
#define B_     16
#define HH     28
#define WW     28
#define HW     784
#define C_ALL  3072
#define C4     2048
#define C3     1024
#define H4     14
#define HW4    196
#define NL     9
#define NK     2000

#define NCH4   32   // l4 chunks (64 ch each) over 2048, contraction at 14x14
#define NCH3   16   // l3 chunks (64 ch each) over 1024, contraction at 28x28

// Output layout: class_scores (16*2000), maps (16*9*784), all_features (16*3072*9)
#define CLS_OFF  0
#define MAPS_OFF (B_*NK)                  // 32000
#define FEAT_OFF (MAPS_OFF + B_*NL*HW)    // 144896

// Scratch (static __device__ arrays: allocation-free)
__device__ float g_asq[NL];
__device__ float g_p4[(size_t)B_*NCH4*NL*HW4];        // 3.6 MB partial ab4 [b][ch][l][q]
__device__ float g_part3[(size_t)NCH3*B_*NL*HW];      // 7.2 MB partial ab3 [ch][b][l][px]
__device__ float g_ab4[(size_t)B_*NL*HW4];            // summed ab4 (14x14)
__device__ float g_ab3[(size_t)B_*NL*HW];             // summed ab3 (28x28)
__device__ float g_md[(size_t)B_*NL*HW4];             // adjoint-downsampled maps
__device__ float g_modavg[(size_t)C_ALL*B_];          // [c][b]

// ---------------------------------------------------------------------------
// K0: a_sq[l] = ||W_land[l]||^2  (one block per landmark)
// ---------------------------------------------------------------------------
__global__ void k_asq(const float* __restrict__ Wl) {
    int l = blockIdx.x, tid = threadIdx.x, warp = tid >> 5, lane = tid & 31;
    __shared__ float red[8];
    float s = 0.f;
    for (int i = tid; i < C_ALL; i += 256) {
        float w = Wl[l * C_ALL + i];
        s = fmaf(w, w, s);
    }
    #pragma unroll
    for (int o = 16; o; o >>= 1) s += __shfl_xor_sync(0xffffffffu, s, o);
    if (lane == 0) red[warp] = s;
    __syncthreads();
    if (tid == 0) {
        float t = 0.f;
        #pragma unroll
        for (int w = 0; w < 8; w++) t += red[w];
        g_asq[l] = t;
    }
}

// ---------------------------------------------------------------------------
// K1: fused landmark-logit contraction.
//  chunk <  NCH4 : ab4 partials at 14x14 over 64 l4 channels (no upsample!)
//  chunk >= NCH4 : ab3 partials at 28x28 over 64 l3 channels
// Weights staged transposed [c][12] so each channel's 9 weights are 2xLDS.128+LDS.
// ---------------------------------------------------------------------------
__global__ __launch_bounds__(196, 4) void k_ab(const float* __restrict__ l3,
                                               const float* __restrict__ l4,
                                               const float* __restrict__ Wl) {
    __shared__ float sWt[64 * 12];      // 3 KB, [c][l] padded to 12
    __shared__ float sRow[8 * HW4];     // 6.1 KB

    int b = blockIdx.y, chunk = blockIdx.x, tid = threadIdx.x;

    if (chunk < NCH4) {
        int c0 = chunk * 64;
        for (int i = tid; i < 64 * NL; i += 196) {
            int c = i / 9, l = i - c * 9;
            sWt[c * 12 + l] = Wl[l * C_ALL + c0 + c];
        }
        const float* l4b = l4 + ((size_t)b * C4 + c0) * HW4;

        float acc[NL];
        #pragma unroll
        for (int l = 0; l < NL; l++) acc[l] = 0.f;

        __syncthreads();
        for (int cg = 0; cg < 64; cg += 8) {
            const float4* src = (const float4*)(l4b + (size_t)cg * HW4);
            ((float4*)sRow)[tid]       = src[tid];
            ((float4*)sRow)[tid + 196] = src[tid + 196];
            __syncthreads();
            #pragma unroll
            for (int cc = 0; cc < 8; cc++) {
                float x = sRow[cc * HW4 + tid];
                int c = cg + cc;
                float4 wa = *(const float4*)&sWt[c * 12];
                float4 wb = *(const float4*)&sWt[c * 12 + 4];
                float  w8 = sWt[c * 12 + 8];
                acc[0] = fmaf(wa.x, x, acc[0]);
                acc[1] = fmaf(wa.y, x, acc[1]);
                acc[2] = fmaf(wa.z, x, acc[2]);
                acc[3] = fmaf(wa.w, x, acc[3]);
                acc[4] = fmaf(wb.x, x, acc[4]);
                acc[5] = fmaf(wb.y, x, acc[5]);
                acc[6] = fmaf(wb.z, x, acc[6]);
                acc[7] = fmaf(wb.w, x, acc[7]);
                acc[8] = fmaf(w8,   x, acc[8]);
            }
            __syncthreads();
        }
        float* dst = g_p4 + ((size_t)(b * NCH4 + chunk) * NL) * HW4 + tid;
        #pragma unroll
        for (int l = 0; l < NL; l++) dst[(size_t)l * HW4] = acc[l];
    } else {
        int ch3 = chunk - NCH4;
        int c0 = ch3 * 64;
        for (int i = tid; i < 64 * NL; i += 196) {
            int c = i / 9, l = i - c * 9;
            sWt[c * 12 + l] = Wl[l * C_ALL + C4 + c0 + c];
        }
        int px = tid * 4;

        float4 acc4[NL];
        #pragma unroll
        for (int l = 0; l < NL; l++) acc4[l] = make_float4(0.f, 0.f, 0.f, 0.f);

        const float* x3 = l3 + ((size_t)b * C3 + c0) * HW + px;
        __syncthreads();
        #pragma unroll 4
        for (int c = 0; c < 64; c++) {
            float4 xv = *(const float4*)(x3 + (size_t)c * HW);
            float4 wa = *(const float4*)&sWt[c * 12];
            float4 wb = *(const float4*)&sWt[c * 12 + 4];
            float  w8 = sWt[c * 12 + 8];
            float ws[NL] = {wa.x, wa.y, wa.z, wa.w, wb.x, wb.y, wb.z, wb.w, w8};
            #pragma unroll
            for (int l = 0; l < NL; l++) {
                acc4[l].x = fmaf(ws[l], xv.x, acc4[l].x);
                acc4[l].y = fmaf(ws[l], xv.y, acc4[l].y);
                acc4[l].z = fmaf(ws[l], xv.z, acc4[l].z);
                acc4[l].w = fmaf(ws[l], xv.w, acc4[l].w);
            }
        }
        // coalesced float4 stores: [ch][b][l][px]
        float* base = g_part3 + (((size_t)ch3 * B_ + b) * NL) * HW + px;
        #pragma unroll
        for (int l = 0; l < NL; l++)
            *(float4*)(base + (size_t)l * HW) = acc4[l];
    }
}

// ---------------------------------------------------------------------------
// K2: reduce partials (both ab4 and ab3, one launch, fully coalesced)
// ---------------------------------------------------------------------------
__global__ void k_red() {
    int idx = blockIdx.x * 256 + threadIdx.x;
    if (idx < B_ * NL * HW4) {
        int b = idx / (NL * HW4), r = idx - b * (NL * HW4);
        const float* p = g_p4 + (size_t)b * NCH4 * NL * HW4 + r;
        float s = 0.f;
        #pragma unroll
        for (int ch = 0; ch < NCH4; ch++) s += p[(size_t)ch * NL * HW4];
        g_ab4[idx] = s;
    } else {
        int j = idx - B_ * NL * HW4;
        if (j >= B_ * NL * HW) return;
        const float* p = g_part3 + j;
        float s = 0.f;
        #pragma unroll
        for (int ch = 0; ch < NCH3; ch++) s += p[(size_t)ch * B_ * NL * HW];
        g_ab3[j] = s;
    }
}

// ---------------------------------------------------------------------------
// K3: upsample ab4 (9 channels only), add ab3, softmax, write maps.
// ---------------------------------------------------------------------------
__global__ void k_softmax(float* __restrict__ out) {
    int idx = blockIdx.x * blockDim.x + threadIdx.x;
    if (idx >= B_ * HW) return;
    int b = idx / HW, px = idx - b * HW;
    int py = px / WW, pxx = px - py * WW;

    float cyf = 0.5f * (float)py - 0.25f;
    int iyf = (int)floorf(cyf);
    float wy = cyf - (float)iyf;
    int iy0 = iyf < 0 ? 0 : iyf;
    int iy1 = (iyf + 1) > 13 ? 13 : (iyf + 1);
    float cxf = 0.5f * (float)pxx - 0.25f;
    int ixf = (int)floorf(cxf);
    float wx = cxf - (float)ixf;
    int ix0 = ixf < 0 ? 0 : ixf;
    int ix1 = (ixf + 1) > 13 ? 13 : (ixf + 1);
    int oa0 = iy0 * H4 + ix0, oa1 = iy0 * H4 + ix1;
    int ob0 = iy1 * H4 + ix0, ob1 = iy1 * H4 + ix1;

    float s[NL];
    const float* A = g_ab4 + (size_t)b * NL * HW4;
    const float* A3 = g_ab3 + (size_t)b * NL * HW + px;
    #pragma unroll
    for (int l = 0; l < NL; l++) {
        const float* r = A + l * HW4;
        float a0 = r[oa0], a1 = r[oa1], b0 = r[ob0], b1 = r[ob1];
        float t = fmaf(wx, a1 - a0, a0);
        float u = fmaf(wx, b1 - b0, b0);
        s[l] = fmaf(wy, u - t, t) + A3[(size_t)l * HW];
    }

    float lg[NL], m = -1e30f;
    #pragma unroll
    for (int l = 0; l < NL; l++) {
        lg[l] = 2.f * s[l] - g_asq[l];
        m = fmaxf(m, lg[l]);
    }
    float e[NL], den = 0.f;
    #pragma unroll
    for (int l = 0; l < NL; l++) { e[l] = __expf(lg[l] - m); den += e[l]; }
    float inv = 1.f / den;

    float* mp = out + MAPS_OFF + (size_t)b * NL * HW + px;
    #pragma unroll
    for (int l = 0; l < NL; l++) mp[(size_t)l * HW] = e[l] * inv;
}

// ---------------------------------------------------------------------------
// K4: adjoint-downsample of maps: md[b][l][q] = sum_px maps[b][l][px]*w(px,q).
// ---------------------------------------------------------------------------
__global__ void k_mapsdown(const float* __restrict__ out) {
    int idx = blockIdx.x * 256 + threadIdx.x;
    if (idx >= B_ * NL * HW4) return;
    int b = idx / (NL * HW4), r = idx - b * (NL * HW4);
    int l = r / HW4, q = r - l * HW4;
    int iy = q / H4, ix = q - iy * H4;

    const float* mp = out + MAPS_OFF + ((size_t)b * NL + l) * HW;

    float s = 0.f;
    #pragma unroll
    for (int dy = 0; dy < 4; dy++) {
        int py = 2 * iy - 1 + dy;
        if (py < 0 || py > 27) continue;
        float cy = 0.5f * (float)py - 0.25f;
        int iyf = (int)floorf(cy);
        float wy = cy - (float)iyf;
        int r0 = iyf < 0 ? 0 : iyf;
        int r1 = (iyf + 1) > 13 ? 13 : (iyf + 1);
        float wr = (r0 == iy ? 1.f - wy : 0.f) + (r1 == iy ? wy : 0.f);
        if (wr == 0.f) continue;
        #pragma unroll
        for (int dx = 0; dx < 4; dx++) {
            int pxx = 2 * ix - 1 + dx;
            if (pxx < 0 || pxx > 27) continue;
            float cx = 0.5f * (float)pxx - 0.25f;
            int ixf = (int)floorf(cx);
            float wxv = cx - (float)ixf;
            int c0 = ixf < 0 ? 0 : ixf;
            int c1 = (ixf + 1) > 13 ? 13 : (ixf + 1);
            float wc = (c0 == ix ? 1.f - wxv : 0.f) + (c1 == ix ? wxv : 0.f);
            if (wc == 0.f) continue;
            s = fmaf(wr * wc, mp[py * WW + pxx], s);
        }
    }
    g_md[idx] = s;
}

// ---------------------------------------------------------------------------
// K5: all_features (+fused modulation average). Thread owns one (c,l) output.
//  cg <  64 : l4 channels, K=196 against g_md   (adjoint trick)
//  cg >= 64 : l3 channels, K=784 against maps (4 px-chunks of 196)
// ---------------------------------------------------------------------------
__global__ __launch_bounds__(288) void k_feat(const float* __restrict__ l3,
                                              const float* __restrict__ l4,
                                              const float* __restrict__ mod,
                                              float* __restrict__ out) {
    __shared__ float4 sX[32 * 49];   // 32 channels x 196 px
    __shared__ float4 sM[NL * 49];   // 9 maps x 196 px
    __shared__ float  sF[288];

    int b = blockIdx.y, cg = blockIdx.x, tid = threadIdx.x;
    int c_local = tid / 9, l = tid - c_local * 9;

    float4 a = make_float4(0.f, 0.f, 0.f, 0.f);
    int cglobal;

    if (cg < 64) {
        int c0 = cg * 32;
        cglobal = c0 + c_local;
        const float4* md4 = (const float4*)(g_md + (size_t)b * NL * HW4);
        for (int i = tid; i < NL * 49; i += 288) sM[i] = md4[i];
        const float4* src = (const float4*)(l4 + ((size_t)b * C4 + c0) * HW4);
        for (int i = tid; i < 32 * 49; i += 288) sX[i] = src[i];
        __syncthreads();

        const float4* xr = sX + c_local * 49;
        const float4* mr = sM + l * 49;
        #pragma unroll 7
        for (int i = 0; i < 49; i++) {
            float4 x = xr[i], m = mr[i];
            a.x = fmaf(x.x, m.x, a.x);
            a.y = fmaf(x.y, m.y, a.y);
            a.z = fmaf(x.z, m.z, a.z);
            a.w = fmaf(x.w, m.w, a.w);
        }
    } else {
        int c0 = (cg - 64) * 32;   // within l3
        cglobal = C4 + c0 + c_local;
        const float* mbase = out + MAPS_OFF + (size_t)b * NL * HW;
        const float* xbase = l3 + ((size_t)b * C3 + c0) * HW;

        for (int pc = 0; pc < 4; pc++) {
            for (int i = tid; i < NL * 49; i += 288) {
                int ll = i / 49, j = i - ll * 49;
                sM[i] = ((const float4*)(mbase + (size_t)ll * HW + pc * HW4))[j];
            }
            for (int i = tid; i < 32 * 49; i += 288) {
                int cc = i / 49, j = i - cc * 49;
                sX[i] = ((const float4*)(xbase + (size_t)cc * HW + pc * HW4))[j];
            }
            __syncthreads();
            const float4* xr = sX + c_local * 49;
            const float4* mr = sM + l * 49;
            #pragma unroll 7
            for (int i = 0; i < 49; i++) {
                float4 x = xr[i], m = mr[i];
                a.x = fmaf(x.x, m.x, a.x);
                a.y = fmaf(x.y, m.y, a.y);
                a.z = fmaf(x.z, m.z, a.z);
                a.w = fmaf(x.w, m.w, a.w);
            }
            __syncthreads();
        }
    }

    float res = ((a.x + a.y) + (a.z + a.w)) * (1.0f / (float)HW);
    out[FEAT_OFF + ((size_t)b * C_ALL + cglobal) * NL + l] = res;

    // fused modulation average: modavg[c][b] = (1/8) sum_{l<8} feat*mod
    sF[tid] = res * mod[cglobal * NL + l];
    __syncthreads();
    if (l == 0) {
        float s = 0.f;
        #pragma unroll
        for (int l2 = 0; l2 < 8; l2++) s += sF[tid + l2];
        g_modavg[(size_t)cglobal * B_ + b] = s * 0.125f;
    }
}

// ---------------------------------------------------------------------------
// K6: class_scores[b,k] = sum_c W_class[k,c] * mod_avg[c][b]
// ---------------------------------------------------------------------------
__global__ __launch_bounds__(256) void k_cls(const float* __restrict__ Wc,
                                             float* __restrict__ out) {
    int k = blockIdx.x, tid = threadIdx.x, warp = tid >> 5, lane = tid & 31;
    const float* wr = Wc + (size_t)k * C_ALL;

    float acc[B_];
    #pragma unroll
    for (int b = 0; b < B_; b++) acc[b] = 0.f;

    for (int c = tid; c < C_ALL; c += 256) {
        float w = wr[c];
        const float4* mv = (const float4*)(g_modavg + (size_t)c * B_);
        #pragma unroll
        for (int q = 0; q < 4; q++) {
            float4 m = mv[q];
            acc[4 * q + 0] = fmaf(w, m.x, acc[4 * q + 0]);
            acc[4 * q + 1] = fmaf(w, m.y, acc[4 * q + 1]);
            acc[4 * q + 2] = fmaf(w, m.z, acc[4 * q + 2]);
            acc[4 * q + 3] = fmaf(w, m.w, acc[4 * q + 3]);
        }
    }

    __shared__ float red[8][B_];
    #pragma unroll
    for (int b = 0; b < B_; b++) {
        float v = acc[b];
        #pragma unroll
        for (int o = 16; o; o >>= 1) v += __shfl_xor_sync(0xffffffffu, v, o);
        acc[b] = v;
    }
    if (lane == 0)
        #pragma unroll
        for (int b = 0; b < B_; b++) red[warp][b] = acc[b];
    __syncthreads();
    if (tid < B_) {
        float s = 0.f;
        #pragma unroll
        for (int w = 0; w < 8; w++) s += red[w][tid];
        out[(size_t)tid * NK + k] = s;
    }
}

// ---------------------------------------------------------------------------
extern "C" void kernel_launch(void* const* d_in, const int* in_sizes, int n_in,
                              void* d_out, int out_size) {
    const float* l3  = (const float*)d_in[0];
    const float* l4  = (const float*)d_in[1];
    const float* Wl  = (const float*)d_in[2];
    const float* Wc  = (const float*)d_in[3];
    const float* mod = (const float*)d_in[4];
    float* out = (float*)d_out;

    k_asq<<<NL, 256>>>(Wl);
    k_ab<<<dim3(NCH4 + NCH3, B_), 196>>>(l3, l4, Wl);
    k_red<<<(B_ * NL * (HW4 + HW) + 255) / 256, 256>>>();
    k_softmax<<<(B_ * HW + 255) / 256, 256>>>(out);
    k_mapsdown<<<(B_ * NL * HW4 + 255) / 256, 256>>>(out);
    k_feat<<<dim3(96, B_), 288>>>(l3, l4, mod, out);
    k_cls<<<NK, 256>>>(Wc, out);
}